// round 8
// baseline (speedup 1.0000x reference)
#include <cuda_runtime.h>
#include <cuda_bf16.h>
#include <math.h>

#define MAXN   2048
#define NW     (MAXN / 64)
#define OUT_N  1000          // POST_NMS_TOP_N

// ---------------- device scratch ----------------
__device__ int                g_order[MAXN];
__device__ float2             g_pts[MAXN][4];
__device__ float4             g_meta[MAXN];        // xc, yc, area, circumradius
__device__ unsigned long long g_mask[MAXN * NW];

// ---------------- kernel 1: stable rank of -scores ---------------------------
__global__ void rank_kernel(const float* __restrict__ scores, int n) {
    int i = blockIdx.x;
    if (i >= n) return;
    float s = scores[i];
    int t = threadIdx.x;
    int cnt = 0;
    for (int j = t; j < n; j += 256) {
        float sj = scores[j];
        cnt += (sj > s) || (sj == s && j < i);
    }
    __shared__ int red[256];
    red[t] = cnt;
    __syncthreads();
    for (int o = 128; o > 0; o >>= 1) {
        if (t < o) red[t] += red[t + o];
        __syncthreads();
    }
    if (t == 0) g_order[red[0]] = i;
}

// ---------------- kernel 2: corners + meta in sorted order -------------------
__global__ void corner_kernel(const float* __restrict__ boxes, int n) {
    int k = blockIdx.x * blockDim.x + threadIdx.x;
    if (k >= n) return;
    int i = g_order[k];
    float xc = boxes[i * 5 + 0];
    float yc = boxes[i * 5 + 1];
    float w  = boxes[i * 5 + 2];
    float h  = boxes[i * 5 + 3];
    float th = boxes[i * 5 + 4];
    float a = th * 0.017453292519943295f;
    float c = cosf(a), s = sinf(a);
    float dx = w * 0.5f, dy = h * 0.5f;
    const float lx[4] = { -dx, dx, dx, -dx };
    const float ly[4] = { -dy, -dy, dy, dy };
#pragma unroll
    for (int e = 0; e < 4; e++) {
        g_pts[k][e] = make_float2(xc + lx[e] * c - ly[e] * s,
                                  yc + lx[e] * s + ly[e] * c);
    }
    g_meta[k] = make_float4(xc, yc, w * h, 0.5f * sqrtf(w * w + h * h));
}

// ---------------- Sutherland-Hodgman quad-quad intersection area -------------
__device__ __forceinline__ float inter_area(const float2 A[4], const float2 B[4]) {
    float px[8], py[8];
#pragma unroll
    for (int k = 0; k < 4; k++) { px[k] = A[k].x; py[k] = A[k].y; }
    int cnt = 4;
#pragma unroll
    for (int e = 0; e < 4; e++) {
        float ax = B[e].x, ay = B[e].y;
        float bx = B[(e + 1) & 3].x, by = B[(e + 1) & 3].y;
        float ex = bx - ax, ey = by - ay;
        float d[8];
#pragma unroll
        for (int k = 0; k < 8; k++)
            d[k] = (k < cnt) ? (ex * (py[k] - ay) - ey * (px[k] - ax)) : 0.0f;
        float ox[8], oy[8];
        int oc = 0;
#pragma unroll
        for (int k = 0; k < 8; k++) {
            if (k < cnt) {
                int kn = (k + 1 < cnt) ? k + 1 : 0;
                bool ic  = d[k]  >= 0.0f;
                bool in_ = d[kn] >= 0.0f;
                if (ic && oc < 8) { ox[oc] = px[k]; oy[oc] = py[k]; oc++; }
                if ((ic != in_) && oc < 8) {
                    float den = d[k] - d[kn];
                    float tp = (fabsf(den) > 1e-12f) ? (d[k] / den) : 0.0f;
                    ox[oc] = px[k] + tp * (px[kn] - px[k]);
                    oy[oc] = py[k] + tp * (py[kn] - py[k]);
                    oc++;
                }
            }
        }
        cnt = oc;
#pragma unroll
        for (int k = 0; k < 8; k++)
            if (k < cnt) { px[k] = ox[k]; py[k] = oy[k]; }
    }
    float ar = 0.0f;
#pragma unroll
    for (int k = 0; k < 8; k++) {
        if (k < cnt) {
            int kn = (k + 1 < cnt) ? k + 1 : 0;
            ar += px[k] * py[kn] - px[kn] * py[k];
        }
    }
    return fmaxf(0.5f * ar, 0.0f);
}

// ---------------- kernel 3: warp per (row, 64-col word), ballot mask ---------
__global__ void mask2_kernel(int n) {
    const int i    = blockIdx.y;
    const int w    = blockIdx.x;
    const int lane = threadIdx.x;
    if (i >= n) return;
    float4 mi = g_meta[i];
    float2 A[4];
#pragma unroll
    for (int e = 0; e < 4; e++) A[e] = g_pts[i][e];
    unsigned long long bits = 0ULL;
#pragma unroll
    for (int half = 0; half < 2; half++) {
        int j = w * 64 + half * 32 + lane;
        bool sup = false;
        if (j < n && j > i) {
            float4 mj = g_meta[j];
            float ddx = mi.x - mj.x, ddy = mi.y - mj.y;
            float rr  = mi.w + mj.w;
            bool pass = (ddx * ddx + ddy * ddy <= rr * rr);   // exact disjointness prune
            float amin = fminf(mi.z, mj.z), amax = fmaxf(mi.z, mj.z);
            pass = pass && (amin > 0.695f * amax);            // IoU <= amin/amax bound
            if (pass) {
                float2 B[4];
#pragma unroll
                for (int e = 0; e < 4; e++) B[e] = g_pts[j][e];
                float inter = inter_area(A, B);
                float u = fmaxf(mi.z + mj.z - inter, 1e-9f);
                sup = (inter / u) > 0.7f;
            }
        }
        unsigned m = __ballot_sync(0xffffffffu, sup);
        bits |= ((unsigned long long)m) << (half * 32);
    }
    if (lane == 0) g_mask[(size_t)i * NW + w] = bits;
}

// ---------------- kernel 4: chunked greedy reduce + float32 emission ---------
__global__ void reduce_kernel(int n, float* __restrict__ out) {
    __shared__ unsigned long long sup[NW];
    __shared__ unsigned long long diag[64];
    __shared__ unsigned long long liveSh;

    int t = threadIdx.x;     // 64 threads
    int nw = (n + 63) / 64;

    if (t < NW) sup[t] = ~0ULL;
    __syncthreads();
    if (t < nw) {
        int rem = n - t * 64;
        sup[t] = (rem >= 64) ? 0ULL : (~0ULL << rem);
    }
    __syncthreads();

    for (int c = 0; c < nw; c++) {
        int base = c * 64;
        int r = base + t;
        diag[t] = (r < n) ? g_mask[(size_t)r * NW + c] : 0ULL;
        __syncthreads();

        if (t == 0) {
            unsigned long long live = ~sup[c];
            unsigned long long fin = 0ULL;
            for (int b = 0; b < 64; b++) {
                unsigned long long bit = 1ULL << b;
                if (live & bit) { fin |= bit; live &= ~diag[b]; }
            }
            sup[c] = ~fin;
            liveSh = fin;
        }
        __syncthreads();

        unsigned long long lf = liveSh;
        if (t < nw && t > c) {
            unsigned long long acc = 0ULL;
            for (int b = 0; b < 64; b++) {
                unsigned long long row = g_mask[(size_t)(base + b) * NW + t];
                unsigned long long m = 0ULL - ((lf >> b) & 1ULL);
                acc |= row & m;
            }
            sup[t] |= acc;
        }
        __syncthreads();
    }

    // Serial emission of exactly OUT_N float32 values: kept original indices
    // in ascending sorted order, then -1 padding.
    if (t == 0) {
        int pos = 0;
        for (int wd = 0; wd < nw && pos < OUT_N; wd++) {
            unsigned long long kw = ~sup[wd];
            while (kw != 0ULL && pos < OUT_N) {
                int b = __ffsll((long long)kw) - 1;
                kw &= kw - 1ULL;
                out[pos++] = (float)g_order[wd * 64 + b];
            }
        }
        while (pos < OUT_N) out[pos++] = -1.0f;
    }
}

// ---------------- launch -----------------------------------------------------
extern "C" void kernel_launch(void* const* d_in, const int* in_sizes, int n_in,
                              void* d_out, int out_size) {
    const float* boxes;
    const float* scores;
    int n;
    if (n_in >= 2 && in_sizes[0] == 5 * in_sizes[1]) {
        boxes = (const float*)d_in[0]; scores = (const float*)d_in[1]; n = in_sizes[1];
    } else if (n_in >= 2 && in_sizes[1] == 5 * in_sizes[0]) {
        boxes = (const float*)d_in[1]; scores = (const float*)d_in[0]; n = in_sizes[0];
    } else {
        boxes = (const float*)d_in[0]; scores = (const float*)d_in[1]; n = in_sizes[1];
    }
    if (n > MAXN) n = MAXN;
    float* out = (float*)d_out;
    int nw = (n + 63) / 64;

    rank_kernel<<<n, 256>>>(scores, n);
    corner_kernel<<<(n + 127) / 128, 128>>>(boxes, n);
    mask2_kernel<<<dim3(nw, n), 32>>>(n);
    reduce_kernel<<<1, 64>>>(n, out);      // writes exactly 1000 float32 values
}

// round 9
// speedup vs baseline: 3.1915x; 3.1915x over previous
#include <cuda_runtime.h>
#include <cuda_bf16.h>
#include <math.h>

#define MAXN   2048
#define NW     (MAXN / 64)
#define OUT_N  1000          // POST_NMS_TOP_N

// ---------------- device scratch ----------------
__device__ int                g_order[MAXN];
__device__ float2             g_pts[MAXN][4];
__device__ float4             g_meta[MAXN];        // xc, yc, area, circumradius
__device__ unsigned long long g_mask[MAXN * NW];

// ---------------- kernel 1: stable rank of -scores ---------------------------
__global__ void rank_kernel(const float* __restrict__ scores, int n) {
    int i = blockIdx.x;
    if (i >= n) return;
    float s = scores[i];
    int t = threadIdx.x;
    int cnt = 0;
    for (int j = t; j < n; j += 256) {
        float sj = scores[j];
        cnt += (sj > s) || (sj == s && j < i);
    }
    __shared__ int red[256];
    red[t] = cnt;
    __syncthreads();
    for (int o = 128; o > 0; o >>= 1) {
        if (t < o) red[t] += red[t + o];
        __syncthreads();
    }
    if (t == 0) g_order[red[0]] = i;
}

// ---------------- kernel 2: corners + meta in sorted order -------------------
__global__ void corner_kernel(const float* __restrict__ boxes, int n) {
    int k = blockIdx.x * blockDim.x + threadIdx.x;
    if (k >= n) return;
    int i = g_order[k];
    float xc = boxes[i * 5 + 0];
    float yc = boxes[i * 5 + 1];
    float w  = boxes[i * 5 + 2];
    float h  = boxes[i * 5 + 3];
    float th = boxes[i * 5 + 4];
    float a = th * 0.017453292519943295f;
    float c = cosf(a), s = sinf(a);
    float dx = w * 0.5f, dy = h * 0.5f;
    const float lx[4] = { -dx, dx, dx, -dx };
    const float ly[4] = { -dy, -dy, dy, dy };
#pragma unroll
    for (int e = 0; e < 4; e++) {
        g_pts[k][e] = make_float2(xc + lx[e] * c - ly[e] * s,
                                  yc + lx[e] * s + ly[e] * c);
    }
    g_meta[k] = make_float4(xc, yc, w * h, 0.5f * sqrtf(w * w + h * h));
}

// ---------------- Sutherland-Hodgman quad-quad intersection area -------------
__device__ __forceinline__ float inter_area(const float2 A[4], const float2 B[4]) {
    float px[8], py[8];
#pragma unroll
    for (int k = 0; k < 4; k++) { px[k] = A[k].x; py[k] = A[k].y; }
    int cnt = 4;
#pragma unroll
    for (int e = 0; e < 4; e++) {
        float ax = B[e].x, ay = B[e].y;
        float bx = B[(e + 1) & 3].x, by = B[(e + 1) & 3].y;
        float ex = bx - ax, ey = by - ay;
        float d[8];
#pragma unroll
        for (int k = 0; k < 8; k++)
            d[k] = (k < cnt) ? (ex * (py[k] - ay) - ey * (px[k] - ax)) : 0.0f;
        float ox[8], oy[8];
        int oc = 0;
#pragma unroll
        for (int k = 0; k < 8; k++) {
            if (k < cnt) {
                int kn = (k + 1 < cnt) ? k + 1 : 0;
                bool ic  = d[k]  >= 0.0f;
                bool in_ = d[kn] >= 0.0f;
                if (ic && oc < 8) { ox[oc] = px[k]; oy[oc] = py[k]; oc++; }
                if ((ic != in_) && oc < 8) {
                    float den = d[k] - d[kn];
                    float tp = (fabsf(den) > 1e-12f) ? (d[k] / den) : 0.0f;
                    ox[oc] = px[k] + tp * (px[kn] - px[k]);
                    oy[oc] = py[k] + tp * (py[kn] - py[k]);
                    oc++;
                }
            }
        }
        cnt = oc;
#pragma unroll
        for (int k = 0; k < 8; k++)
            if (k < cnt) { px[k] = ox[k]; py[k] = oy[k]; }
    }
    float ar = 0.0f;
#pragma unroll
    for (int k = 0; k < 8; k++) {
        if (k < cnt) {
            int kn = (k + 1 < cnt) ? k + 1 : 0;
            ar += px[k] * py[kn] - px[kn] * py[k];
        }
    }
    return fmaxf(0.5f * ar, 0.0f);
}

// ---------------- kernel 3: warp per (row, 64-col word), ballot mask ---------
__global__ void mask2_kernel(int n) {
    const int i    = blockIdx.y;
    const int w    = blockIdx.x;
    const int lane = threadIdx.x;
    if (i >= n) return;
    float4 mi = g_meta[i];
    float2 A[4];
#pragma unroll
    for (int e = 0; e < 4; e++) A[e] = g_pts[i][e];
    unsigned long long bits = 0ULL;
#pragma unroll
    for (int half = 0; half < 2; half++) {
        int j = w * 64 + half * 32 + lane;
        bool sup = false;
        if (j < n && j > i) {
            float4 mj = g_meta[j];
            float ddx = mi.x - mj.x, ddy = mi.y - mj.y;
            float rr  = mi.w + mj.w;
            bool pass = (ddx * ddx + ddy * ddy <= rr * rr);
            float amin = fminf(mi.z, mj.z), amax = fmaxf(mi.z, mj.z);
            pass = pass && (amin > 0.695f * amax);
            if (pass) {
                float2 B[4];
#pragma unroll
                for (int e = 0; e < 4; e++) B[e] = g_pts[j][e];
                float inter = inter_area(A, B);
                float u = fmaxf(mi.z + mj.z - inter, 1e-9f);
                sup = (inter / u) > 0.7f;
            }
        }
        unsigned m = __ballot_sync(0xffffffffu, sup);
        bits |= ((unsigned long long)m) << (half * 32);
    }
    if (lane == 0) g_mask[(size_t)i * NW + w] = bits;
}

// ---------------- kernel 4: parallel chunked greedy reduce -------------------
// 1024 threads: warp w owns chunk rows {w, w+32}, lane = mask word (coalesced).
__global__ void reduce_kernel(int n, float* __restrict__ out) {
    const int tid  = threadIdx.x;
    const int w    = tid >> 5;
    const int lane = tid & 31;
    const int nw   = (n + 63) / 64;

    __shared__ unsigned long long sup[NW];
    __shared__ unsigned long long darr[64];
    __shared__ unsigned long long uarr[32];
    __shared__ unsigned long long finSh;
    __shared__ int keptSh;

    if (tid < NW) {
        if (tid < nw) {
            int rem = n - tid * 64;
            sup[tid] = (rem >= 64) ? 0ULL : (~0ULL << rem);
        } else {
            sup[tid] = ~0ULL;
        }
    }
    __syncthreads();

    for (int c = 0; c < nw; c++) {
        int base = c * 64;
        int r0 = base + w, r1 = base + w + 32;
        // Parallel coalesced slab load (all rows x all words of this chunk)
        unsigned long long m0 = (r0 < n && lane < nw) ? g_mask[(size_t)r0 * NW + lane] : 0ULL;
        unsigned long long m1 = (r1 < n && lane < nw) ? g_mask[(size_t)r1 * NW + lane] : 0ULL;

        unsigned long long live = ~sup[c];

        // Diagonal words (word index == c) extracted via shfl
        unsigned long long d0 = __shfl_sync(0xffffffffu, m0, c);
        unsigned long long d1 = __shfl_sync(0xffffffffu, m1, c);
        if (lane == 0) {
            darr[w]      = d0;
            darr[w + 32] = d1;
            unsigned long long u = 0ULL;
            if ((live >> w) & 1ULL)        u |= d0;
            if ((live >> (w + 32)) & 1ULL) u |= d1;
            uarr[w] = u;
        }
        __syncthreads();

        // Warp 0 resolves intra-chunk greedy (fast path: no live-live suppression)
        if (w == 0) {
            unsigned long long u = uarr[lane];
#pragma unroll
            for (int o = 16; o; o >>= 1) u |= __shfl_xor_sync(0xffffffffu, u, o);
            if (lane == 0) {
                unsigned long long fin;
                if ((u & live) == 0ULL) {
                    fin = live;                       // fast path (common)
                } else {
                    unsigned long long lv = live;     // rare serial fallback
                    fin = 0ULL;
                    for (int b = 0; b < 64; b++) {
                        unsigned long long bit = 1ULL << b;
                        if (lv & bit) { fin |= bit; lv &= ~darr[b]; }
                    }
                }
                finSh = fin;
                sup[c] = ~fin;
            }
        }
        __syncthreads();

        // Cross-chunk update: OR kept rows' mask words into future sup words.
        unsigned long long fin = finSh;
        unsigned long long acc = (m0 & (0ULL - ((fin >> w) & 1ULL)))
                               | (m1 & (0ULL - ((fin >> (w + 32)) & 1ULL)));
        if (acc != 0ULL && lane > c) atomicOr(&sup[lane], acc);
        __syncthreads();
    }

    // Parallel emission: warp 0 prefix-scans keep-counts, each lane emits its word.
    if (w == 0) {
        unsigned long long kw = (lane < nw) ? ~sup[lane] : 0ULL;
        int pc = __popcll(kw);
        int sc = pc;
#pragma unroll
        for (int o = 1; o < 32; o <<= 1) {
            int v = __shfl_up_sync(0xffffffffu, sc, o);
            if (lane >= o) sc += v;
        }
        int excl = sc - pc;
        while (kw) {
            int b = __ffsll((long long)kw) - 1;
            kw &= kw - 1ULL;
            if (excl < OUT_N) out[excl] = (float)g_order[lane * 64 + b];
            excl++;
        }
        if (lane == 31) keptSh = sc;
    }
    __syncthreads();
    int kept = keptSh;
    for (int p = kept + tid; p < OUT_N; p += 1024) out[p] = -1.0f;
}

// ---------------- launch -----------------------------------------------------
extern "C" void kernel_launch(void* const* d_in, const int* in_sizes, int n_in,
                              void* d_out, int out_size) {
    const float* boxes;
    const float* scores;
    int n;
    if (n_in >= 2 && in_sizes[0] == 5 * in_sizes[1]) {
        boxes = (const float*)d_in[0]; scores = (const float*)d_in[1]; n = in_sizes[1];
    } else if (n_in >= 2 && in_sizes[1] == 5 * in_sizes[0]) {
        boxes = (const float*)d_in[1]; scores = (const float*)d_in[0]; n = in_sizes[0];
    } else {
        boxes = (const float*)d_in[0]; scores = (const float*)d_in[1]; n = in_sizes[1];
    }
    if (n > MAXN) n = MAXN;
    float* out = (float*)d_out;
    int nw = (n + 63) / 64;

    rank_kernel<<<n, 256>>>(scores, n);
    corner_kernel<<<(n + 127) / 128, 128>>>(boxes, n);
    mask2_kernel<<<dim3(nw, n), 32>>>(n);
    reduce_kernel<<<1, 1024>>>(n, out);
}

// round 10
// speedup vs baseline: 5.0581x; 1.5848x over previous
#include <cuda_runtime.h>
#include <cuda_bf16.h>
#include <math.h>

#define MAXN   2048
#define NW     (MAXN / 64)
#define OUT_N  1000          // POST_NMS_TOP_N

// ---------------- device scratch ----------------
__device__ int                g_order[MAXN];
__device__ float2             g_pts[MAXN][4];
__device__ float4             g_meta[MAXN];        // xc, yc, area, circumradius
__device__ unsigned long long g_mask[MAXN * NW];

// ---------------- kernel 1: stable rank of -scores ---------------------------
__global__ void rank_kernel(const float* __restrict__ scores, int n) {
    int i = blockIdx.x;
    if (i >= n) return;
    float s = scores[i];
    int t = threadIdx.x;
    int cnt = 0;
    for (int j = t; j < n; j += 256) {
        float sj = scores[j];
        cnt += (sj > s) || (sj == s && j < i);
    }
    __shared__ int red[256];
    red[t] = cnt;
    __syncthreads();
    for (int o = 128; o > 0; o >>= 1) {
        if (t < o) red[t] += red[t + o];
        __syncthreads();
    }
    if (t == 0) g_order[red[0]] = i;
}

// ---------------- kernel 2: corners + meta in sorted order -------------------
__global__ void corner_kernel(const float* __restrict__ boxes, int n) {
    int k = blockIdx.x * blockDim.x + threadIdx.x;
    if (k >= n) return;
    int i = g_order[k];
    float xc = boxes[i * 5 + 0];
    float yc = boxes[i * 5 + 1];
    float w  = boxes[i * 5 + 2];
    float h  = boxes[i * 5 + 3];
    float th = boxes[i * 5 + 4];
    float a = th * 0.017453292519943295f;
    float c = cosf(a), s = sinf(a);
    float dx = w * 0.5f, dy = h * 0.5f;
    const float lx[4] = { -dx, dx, dx, -dx };
    const float ly[4] = { -dy, -dy, dy, dy };
#pragma unroll
    for (int e = 0; e < 4; e++) {
        g_pts[k][e] = make_float2(xc + lx[e] * c - ly[e] * s,
                                  yc + lx[e] * s + ly[e] * c);
    }
    g_meta[k] = make_float4(xc, yc, w * h, 0.5f * sqrtf(w * w + h * h));
}

// ---------------- Sutherland-Hodgman quad-quad intersection area -------------
__device__ __forceinline__ float inter_area(const float2 A[4], const float2 B[4]) {
    float px[8], py[8];
#pragma unroll
    for (int k = 0; k < 4; k++) { px[k] = A[k].x; py[k] = A[k].y; }
    int cnt = 4;
#pragma unroll
    for (int e = 0; e < 4; e++) {
        float ax = B[e].x, ay = B[e].y;
        float bx = B[(e + 1) & 3].x, by = B[(e + 1) & 3].y;
        float ex = bx - ax, ey = by - ay;
        float d[8];
#pragma unroll
        for (int k = 0; k < 8; k++)
            d[k] = (k < cnt) ? (ex * (py[k] - ay) - ey * (px[k] - ax)) : 0.0f;
        float ox[8], oy[8];
        int oc = 0;
#pragma unroll
        for (int k = 0; k < 8; k++) {
            if (k < cnt) {
                int kn = (k + 1 < cnt) ? k + 1 : 0;
                bool ic  = d[k]  >= 0.0f;
                bool in_ = d[kn] >= 0.0f;
                if (ic && oc < 8) { ox[oc] = px[k]; oy[oc] = py[k]; oc++; }
                if ((ic != in_) && oc < 8) {
                    float den = d[k] - d[kn];
                    float tp = (fabsf(den) > 1e-12f) ? (d[k] / den) : 0.0f;
                    ox[oc] = px[k] + tp * (px[kn] - px[k]);
                    oy[oc] = py[k] + tp * (py[kn] - py[k]);
                    oc++;
                }
            }
        }
        cnt = oc;
#pragma unroll
        for (int k = 0; k < 8; k++)
            if (k < cnt) { px[k] = ox[k]; py[k] = oy[k]; }
    }
    float ar = 0.0f;
#pragma unroll
    for (int k = 0; k < 8; k++) {
        if (k < cnt) {
            int kn = (k + 1 < cnt) ? k + 1 : 0;
            ar += px[k] * py[kn] - px[kn] * py[k];
        }
    }
    return fmaxf(0.5f * ar, 0.0f);
}

// ---------------- kernel 3: 64x64 tile, prune->compact->dense clip -----------
__global__ void mask_kernel(int n) {
    const int rb = blockIdx.y, cb = blockIdx.x, t = threadIdx.x;  // 128 threads

    if (cb < rb) {                        // lower-tri blocks: zero and exit
        int i = rb * 64 + t;
        if (t < 64 && i < n) g_mask[(size_t)i * NW + cb] = 0ULL;
        return;
    }

    __shared__ float2 sP[64][4];
    __shared__ float4 sM[64];
    __shared__ unsigned short q[4096];
    __shared__ int qcnt;
    __shared__ unsigned long long rowbits[64];

    if (t == 0) qcnt = 0;
    if (t < 64) {
        rowbits[t] = 0ULL;
        int j = cb * 64 + t;
        if (j < n) {
            sM[t] = g_meta[j];
#pragma unroll
            for (int e = 0; e < 4; e++) sP[t][e] = g_pts[j][e];
        } else {
            sM[t] = make_float4(1e30f, 1e30f, 0.0f, 0.0f);
        }
    }
    __syncthreads();

    // Phase 1: each thread prunes one (row, col-half): 32 candidates
    {
        int r = t >> 1, half = t & 1;
        int i = rb * 64 + r;
        if (i < n) {
            float4 mi = g_meta[i];
            int c0 = half * 32;
            for (int cc = c0; cc < c0 + 32; cc++) {
                int j = cb * 64 + cc;
                if (j >= n) break;
                if (cb == rb && cc <= r) continue;               // only j > i
                float4 mj = sM[cc];
                float ddx = mi.x - mj.x, ddy = mi.y - mj.y;
                float rr  = mi.w + mj.w;
                if (ddx * ddx + ddy * ddy > rr * rr) continue;   // disjoint (exact)
                float amin = fminf(mi.z, mj.z), amax = fmaxf(mi.z, mj.z);
                if (amin <= 0.695f * amax) continue;             // IoU < 0.7 bound
                int pos = atomicAdd(&qcnt, 1);
                if (pos < 4096) q[pos] = (unsigned short)((r << 6) | cc);
            }
        }
    }
    __syncthreads();

    // Phase 2: dense clipping over compacted queue
    int cnt = qcnt > 4096 ? 4096 : qcnt;
    for (int k = t; k < cnt; k += 128) {
        unsigned short pc = q[k];
        int r = pc >> 6, c = pc & 63;
        int ii = rb * 64 + r;
        float2 A[4];
#pragma unroll
        for (int e = 0; e < 4; e++) A[e] = g_pts[ii][e];
        float inter = inter_area(A, sP[c]);
        float aA = g_meta[ii].z, aB = sM[c].z;
        float u = fmaxf(aA + aB - inter, 1e-9f);
        if (inter / u > 0.7f) atomicOr(&rowbits[r], 1ULL << c);
    }
    __syncthreads();

    if (t < 64) {
        int i = rb * 64 + t;
        if (i < n) g_mask[(size_t)i * NW + cb] = rowbits[t];
    }
}

// ---------------- kernel 4: pipelined parallel greedy reduce -----------------
// 1024 threads: warp w owns chunk rows {w, w+32}, lane = mask word (coalesced).
// Next chunk's slab is prefetched while the current one is resolved.
__global__ void reduce_kernel(int n, float* __restrict__ out) {
    const int tid  = threadIdx.x;
    const int w    = tid >> 5;
    const int lane = tid & 31;
    const int nw   = (n + 63) / 64;

    __shared__ unsigned long long sup[NW];
    __shared__ unsigned long long darr[64];
    __shared__ unsigned long long uarr[32];
    __shared__ unsigned long long finSh;
    __shared__ int keptSh;

    if (tid < NW) {
        if (tid < nw) {
            int rem = n - tid * 64;
            sup[tid] = (rem >= 64) ? 0ULL : (~0ULL << rem);
        } else {
            sup[tid] = ~0ULL;
        }
    }
    __syncthreads();

    // Preload chunk 0 slab
    unsigned long long m0 = 0ULL, m1 = 0ULL;
    {
        int r0 = w, r1 = w + 32;
        if (r0 < n && lane < nw) m0 = g_mask[(size_t)r0 * NW + lane];
        if (r1 < n && lane < nw) m1 = g_mask[(size_t)r1 * NW + lane];
    }

    for (int c = 0; c < nw; c++) {
        // Prefetch chunk c+1 slab (g_mask is read-only here; latency hidden)
        unsigned long long p0 = 0ULL, p1 = 0ULL;
        if (c + 1 < nw) {
            int base = (c + 1) * 64;
            int r0 = base + w, r1 = base + w + 32;
            if (r0 < n && lane < nw) p0 = g_mask[(size_t)r0 * NW + lane];
            if (r1 < n && lane < nw) p1 = g_mask[(size_t)r1 * NW + lane];
        }

        unsigned long long live = ~sup[c];

        // Diagonal words (word index == c) via shfl
        unsigned long long d0 = __shfl_sync(0xffffffffu, m0, c);
        unsigned long long d1 = __shfl_sync(0xffffffffu, m1, c);
        if (lane == 0) {
            darr[w]      = d0;
            darr[w + 32] = d1;
            unsigned long long u = 0ULL;
            if ((live >> w) & 1ULL)        u |= d0;
            if ((live >> (w + 32)) & 1ULL) u |= d1;
            uarr[w] = u;
        }
        __syncthreads();

        // Warp 0 resolves intra-chunk greedy (fast path: no live-live suppression)
        if (w == 0) {
            unsigned long long u = uarr[lane];
#pragma unroll
            for (int o = 16; o; o >>= 1) u |= __shfl_xor_sync(0xffffffffu, u, o);
            if (lane == 0) {
                unsigned long long fin;
                if ((u & live) == 0ULL) {
                    fin = live;                       // fast path (common)
                } else {
                    unsigned long long lv = live;     // rare serial fallback
                    fin = 0ULL;
                    for (int b = 0; b < 64; b++) {
                        unsigned long long bit = 1ULL << b;
                        if (lv & bit) { fin |= bit; lv &= ~darr[b]; }
                    }
                }
                finSh = fin;
                sup[c] = ~fin;
            }
        }
        __syncthreads();

        // Cross-chunk update: OR kept rows' mask words into future sup words.
        unsigned long long fin = finSh;
        unsigned long long acc = (m0 & (0ULL - ((fin >> w) & 1ULL)))
                               | (m1 & (0ULL - ((fin >> (w + 32)) & 1ULL)));
        if (acc != 0ULL && lane > c) atomicOr(&sup[lane], acc);
        __syncthreads();

        m0 = p0; m1 = p1;
    }

    // Parallel emission: warp 0 prefix-scans keep-counts, each lane emits its word.
    if (w == 0) {
        unsigned long long kw = (lane < nw) ? ~sup[lane] : 0ULL;
        int pc = __popcll(kw);
        int sc = pc;
#pragma unroll
        for (int o = 1; o < 32; o <<= 1) {
            int v = __shfl_up_sync(0xffffffffu, sc, o);
            if (lane >= o) sc += v;
        }
        int excl = sc - pc;
        while (kw) {
            int b = __ffsll((long long)kw) - 1;
            kw &= kw - 1ULL;
            if (excl < OUT_N) out[excl] = (float)g_order[lane * 64 + b];
            excl++;
        }
        if (lane == 31) keptSh = sc;
    }
    __syncthreads();
    int kept = keptSh;
    for (int p = kept + tid; p < OUT_N; p += 1024) out[p] = -1.0f;
}

// ---------------- launch -----------------------------------------------------
extern "C" void kernel_launch(void* const* d_in, const int* in_sizes, int n_in,
                              void* d_out, int out_size) {
    const float* boxes;
    const float* scores;
    int n;
    if (n_in >= 2 && in_sizes[0] == 5 * in_sizes[1]) {
        boxes = (const float*)d_in[0]; scores = (const float*)d_in[1]; n = in_sizes[1];
    } else if (n_in >= 2 && in_sizes[1] == 5 * in_sizes[0]) {
        boxes = (const float*)d_in[1]; scores = (const float*)d_in[0]; n = in_sizes[0];
    } else {
        boxes = (const float*)d_in[0]; scores = (const float*)d_in[1]; n = in_sizes[1];
    }
    if (n > MAXN) n = MAXN;
    float* out = (float*)d_out;
    int nw = (n + 63) / 64;

    rank_kernel<<<n, 256>>>(scores, n);
    corner_kernel<<<(n + 127) / 128, 128>>>(boxes, n);
    mask_kernel<<<dim3(nw, nw), 128>>>(n);
    reduce_kernel<<<1, 1024>>>(n, out);
}

// round 11
// speedup vs baseline: 5.3873x; 1.0651x over previous
#include <cuda_runtime.h>
#include <cuda_bf16.h>
#include <math.h>

#define MAXN   2048
#define NW     (MAXN / 64)
#define OUT_N  1000          // POST_NMS_TOP_N

// ---------------- device scratch ----------------
__device__ int                g_order[MAXN];
__device__ float2             g_pts[MAXN][4];
__device__ float4             g_meta[MAXN];        // xc, yc, area, circumradius
__device__ unsigned long long g_mask[MAXN * NW];

// ---------------- kernel 1: stable rank of -scores ---------------------------
__global__ void rank_kernel(const float* __restrict__ scores, int n) {
    int i = blockIdx.x;
    if (i >= n) return;
    float s = scores[i];
    int t = threadIdx.x;
    int cnt = 0;
    for (int j = t; j < n; j += 256) {
        float sj = scores[j];
        cnt += (sj > s) || (sj == s && j < i);
    }
    __shared__ int red[256];
    red[t] = cnt;
    __syncthreads();
    for (int o = 128; o > 0; o >>= 1) {
        if (t < o) red[t] += red[t + o];
        __syncthreads();
    }
    if (t == 0) g_order[red[0]] = i;
}

// ---------------- kernel 2: corners + meta in sorted order -------------------
__global__ void corner_kernel(const float* __restrict__ boxes, int n) {
    int k = blockIdx.x * blockDim.x + threadIdx.x;
    if (k >= n) return;
    int i = g_order[k];
    float xc = boxes[i * 5 + 0];
    float yc = boxes[i * 5 + 1];
    float w  = boxes[i * 5 + 2];
    float h  = boxes[i * 5 + 3];
    float th = boxes[i * 5 + 4];
    float a = th * 0.017453292519943295f;
    float c = cosf(a), s = sinf(a);
    float dx = w * 0.5f, dy = h * 0.5f;
    const float lx[4] = { -dx, dx, dx, -dx };
    const float ly[4] = { -dy, -dy, dy, dy };
#pragma unroll
    for (int e = 0; e < 4; e++) {
        g_pts[k][e] = make_float2(xc + lx[e] * c - ly[e] * s,
                                  yc + lx[e] * s + ly[e] * c);
    }
    g_meta[k] = make_float4(xc, yc, w * h, 0.5f * sqrtf(w * w + h * h));
}

// ---------------- Sutherland-Hodgman quad-quad intersection area -------------
__device__ __forceinline__ float inter_area(const float2 A[4], const float2 B[4]) {
    float px[8], py[8];
#pragma unroll
    for (int k = 0; k < 4; k++) { px[k] = A[k].x; py[k] = A[k].y; }
    int cnt = 4;
#pragma unroll
    for (int e = 0; e < 4; e++) {
        float ax = B[e].x, ay = B[e].y;
        float bx = B[(e + 1) & 3].x, by = B[(e + 1) & 3].y;
        float ex = bx - ax, ey = by - ay;
        float d[8];
#pragma unroll
        for (int k = 0; k < 8; k++)
            d[k] = (k < cnt) ? (ex * (py[k] - ay) - ey * (px[k] - ax)) : 0.0f;
        float ox[8], oy[8];
        int oc = 0;
#pragma unroll
        for (int k = 0; k < 8; k++) {
            if (k < cnt) {
                int kn = (k + 1 < cnt) ? k + 1 : 0;
                bool ic  = d[k]  >= 0.0f;
                bool in_ = d[kn] >= 0.0f;
                if (ic && oc < 8) { ox[oc] = px[k]; oy[oc] = py[k]; oc++; }
                if ((ic != in_) && oc < 8) {
                    float den = d[k] - d[kn];
                    float tp = (fabsf(den) > 1e-12f) ? (d[k] / den) : 0.0f;
                    ox[oc] = px[k] + tp * (px[kn] - px[k]);
                    oy[oc] = py[k] + tp * (py[kn] - py[k]);
                    oc++;
                }
            }
        }
        cnt = oc;
#pragma unroll
        for (int k = 0; k < 8; k++)
            if (k < cnt) { px[k] = ox[k]; py[k] = oy[k]; }
    }
    float ar = 0.0f;
#pragma unroll
    for (int k = 0; k < 8; k++) {
        if (k < cnt) {
            int kn = (k + 1 < cnt) ? k + 1 : 0;
            ar += px[k] * py[kn] - px[kn] * py[k];
        }
    }
    return fmaxf(0.5f * ar, 0.0f);
}

// ---------------- kernel 3: 64x64 tile, prune->compact->dense clip -----------
__global__ void mask_kernel(int n) {
    const int rb = blockIdx.y, cb = blockIdx.x, t = threadIdx.x;  // 128 threads

    if (cb < rb) {                        // lower-tri blocks: zero and exit
        int i = rb * 64 + t;
        if (t < 64 && i < n) g_mask[(size_t)i * NW + cb] = 0ULL;
        return;
    }

    __shared__ float2 sP[64][4];
    __shared__ float4 sM[64];
    __shared__ unsigned short q[4096];
    __shared__ int qcnt;
    __shared__ unsigned long long rowbits[64];

    if (t == 0) qcnt = 0;
    if (t < 64) {
        rowbits[t] = 0ULL;
        int j = cb * 64 + t;
        if (j < n) {
            sM[t] = g_meta[j];
#pragma unroll
            for (int e = 0; e < 4; e++) sP[t][e] = g_pts[j][e];
        } else {
            sM[t] = make_float4(1e30f, 1e30f, 0.0f, 0.0f);
        }
    }
    __syncthreads();

    // Phase 1: each thread prunes one (row, col-half): 32 candidates
    {
        int r = t >> 1, half = t & 1;
        int i = rb * 64 + r;
        if (i < n) {
            float4 mi = g_meta[i];
            int c0 = half * 32;
            for (int cc = c0; cc < c0 + 32; cc++) {
                int j = cb * 64 + cc;
                if (j >= n) break;
                if (cb == rb && cc <= r) continue;               // only j > i
                float4 mj = sM[cc];
                float ddx = mi.x - mj.x, ddy = mi.y - mj.y;
                float rr  = mi.w + mj.w;
                if (ddx * ddx + ddy * ddy > rr * rr) continue;   // disjoint (exact)
                float amin = fminf(mi.z, mj.z), amax = fmaxf(mi.z, mj.z);
                if (amin <= 0.695f * amax) continue;             // IoU < 0.7 bound
                int pos = atomicAdd(&qcnt, 1);
                if (pos < 4096) q[pos] = (unsigned short)((r << 6) | cc);
            }
        }
    }
    __syncthreads();

    // Phase 2: dense clipping over compacted queue
    int cnt = qcnt > 4096 ? 4096 : qcnt;
    for (int k = t; k < cnt; k += 128) {
        unsigned short pc = q[k];
        int r = pc >> 6, c = pc & 63;
        int ii = rb * 64 + r;
        float2 A[4];
#pragma unroll
        for (int e = 0; e < 4; e++) A[e] = g_pts[ii][e];
        float inter = inter_area(A, sP[c]);
        float aA = g_meta[ii].z, aB = sM[c].z;
        float u = fmaxf(aA + aB - inter, 1e-9f);
        if (inter / u > 0.7f) atomicOr(&rowbits[r], 1ULL << c);
    }
    __syncthreads();

    if (t < 64) {
        int i = rb * 64 + t;
        if (i < n) g_mask[(size_t)i * NW + cb] = rowbits[t];
    }
}

// ---------------- kernel 4: parallel greedy reduce, sparse chunk resolve -----
// 1024 threads: warp w owns chunk rows {w, w+32}, lane = mask word (coalesced).
// Intra-chunk greedy touches ONLY contested rows (diag & live != 0).
__global__ void reduce_kernel(int n, float* __restrict__ out) {
    const int tid  = threadIdx.x;
    const int w    = tid >> 5;
    const int lane = tid & 31;
    const int nw   = (n + 63) / 64;

    __shared__ unsigned long long sup[NW];
    __shared__ unsigned long long darr[64];
    __shared__ unsigned long long finSh;
    __shared__ int keptSh;

    if (tid < NW) {
        if (tid < nw) {
            int rem = n - tid * 64;
            sup[tid] = (rem >= 64) ? 0ULL : (~0ULL << rem);
        } else {
            sup[tid] = ~0ULL;
        }
    }
    __syncthreads();

    // Preload chunk 0 slab
    unsigned long long m0 = 0ULL, m1 = 0ULL;
    {
        int r0 = w, r1 = w + 32;
        if (r0 < n && lane < nw) m0 = g_mask[(size_t)r0 * NW + lane];
        if (r1 < n && lane < nw) m1 = g_mask[(size_t)r1 * NW + lane];
    }

    for (int c = 0; c < nw; c++) {
        // Prefetch chunk c+1 slab
        unsigned long long p0 = 0ULL, p1 = 0ULL;
        if (c + 1 < nw) {
            int base = (c + 1) * 64;
            int r0 = base + w, r1 = base + w + 32;
            if (r0 < n && lane < nw) p0 = g_mask[(size_t)r0 * NW + lane];
            if (r1 < n && lane < nw) p1 = g_mask[(size_t)r1 * NW + lane];
        }

        // Diagonal words (word index == c) via shfl; warp w owns rows w, w+32
        unsigned long long d0 = __shfl_sync(0xffffffffu, m0, c);
        unsigned long long d1 = __shfl_sync(0xffffffffu, m1, c);
        if (lane == 0) {
            darr[w]      = d0;
            darr[w + 32] = d1;
        }
        __syncthreads();

        // Warp 0: sparse intra-chunk greedy.
        if (w == 0) {
            unsigned long long live = ~sup[c];
            unsigned long long a0 = darr[lane];        // row 'lane'
            unsigned long long a1 = darr[lane + 32];   // row 'lane+32'
            unsigned nzlo = __ballot_sync(0xffffffffu, (a0 & live) != 0ULL);
            unsigned nzhi = __ballot_sync(0xffffffffu, (a1 & live) != 0ULL);
            if (lane == 0) {
                unsigned long long nz = ((unsigned long long)nzhi << 32) | nzlo;
                unsigned long long lv = live;
                unsigned long long m = nz & lv;
                while (m) {
                    int b = __ffsll((long long)m) - 1;
                    m &= m - 1ULL;
                    if ((lv >> b) & 1ULL) {
                        lv &= ~darr[b];     // suppress later rows in this chunk
                        m  &= lv;           // drop contested rows that just died
                    }
                }
                finSh = lv;                 // upper-triangular => lv is final keep set
                sup[c] = ~lv;
            }
        }
        __syncthreads();

        // Cross-chunk update: OR kept rows' mask words into future sup words.
        unsigned long long fin = finSh;
        unsigned long long acc = (m0 & (0ULL - ((fin >> w) & 1ULL)))
                               | (m1 & (0ULL - ((fin >> (w + 32)) & 1ULL)));
        if (acc != 0ULL && lane > c) atomicOr(&sup[lane], acc);
        __syncthreads();

        m0 = p0; m1 = p1;
    }

    // Parallel emission: warp 0 prefix-scans keep-counts, each lane emits its word.
    if (w == 0) {
        unsigned long long kw = (lane < nw) ? ~sup[lane] : 0ULL;
        int pc = __popcll(kw);
        int sc = pc;
#pragma unroll
        for (int o = 1; o < 32; o <<= 1) {
            int v = __shfl_up_sync(0xffffffffu, sc, o);
            if (lane >= o) sc += v;
        }
        int excl = sc - pc;
        while (kw) {
            int b = __ffsll((long long)kw) - 1;
            kw &= kw - 1ULL;
            if (excl < OUT_N) out[excl] = (float)g_order[lane * 64 + b];
            excl++;
        }
        if (lane == 31) keptSh = sc;
    }
    __syncthreads();
    int kept = keptSh;
    for (int p = kept + tid; p < OUT_N; p += 1024) out[p] = -1.0f;
}

// ---------------- launch -----------------------------------------------------
extern "C" void kernel_launch(void* const* d_in, const int* in_sizes, int n_in,
                              void* d_out, int out_size) {
    const float* boxes;
    const float* scores;
    int n;
    if (n_in >= 2 && in_sizes[0] == 5 * in_sizes[1]) {
        boxes = (const float*)d_in[0]; scores = (const float*)d_in[1]; n = in_sizes[1];
    } else if (n_in >= 2 && in_sizes[1] == 5 * in_sizes[0]) {
        boxes = (const float*)d_in[1]; scores = (const float*)d_in[0]; n = in_sizes[0];
    } else {
        boxes = (const float*)d_in[0]; scores = (const float*)d_in[1]; n = in_sizes[1];
    }
    if (n > MAXN) n = MAXN;
    float* out = (float*)d_out;
    int nw = (n + 63) / 64;

    rank_kernel<<<n, 256>>>(scores, n);
    corner_kernel<<<(n + 127) / 128, 128>>>(boxes, n);
    mask_kernel<<<dim3(nw, nw), 128>>>(n);
    reduce_kernel<<<1, 1024>>>(n, out);
}